// round 8
// baseline (speedup 1.0000x reference)
#include <cuda_runtime.h>
#include <math.h>

typedef unsigned long long u64;

#define SPLITK 8

// Split-K partial sums of x @ W^T (bias added in circuit kernel). No allocs.
__device__ float g_com4[SPLITK][1024 * 512];

// ---------------------------------------------------------------------------
// Packed fp32x2 helpers (PTX-only)
// ---------------------------------------------------------------------------
__device__ __forceinline__ u64 pk2(float lo, float hi) {
    u64 d; asm("mov.b64 %0, {%1, %2};" : "=l"(d) : "f"(lo), "f"(hi)); return d;
}
__device__ __forceinline__ u64 fma2(u64 a, u64 b, u64 c) {
    u64 d; asm("fma.rn.f32x2 %0, %1, %2, %3;" : "=l"(d) : "l"(a), "l"(b), "l"(c)); return d;
}
__device__ __forceinline__ u64 mul2(u64 a, u64 b) {
    u64 d; asm("mul.rn.f32x2 %0, %1, %2;" : "=l"(d) : "l"(a), "l"(b)); return d;
}
__device__ __forceinline__ u64 add2(u64 a, u64 b) {
    u64 d; asm("add.rn.f32x2 %0, %1, %2;" : "=l"(d) : "l"(a), "l"(b)); return d;
}
__device__ __forceinline__ void unpk2(float& lo, float& hi, u64 d) {
    asm("mov.b64 {%0, %1}, %2;" : "=f"(lo), "=f"(hi) : "l"(d));
}

// ---------------------------------------------------------------------------
// GEMM v3: split-K partials of x @ W^T.
// BM=128, BN=64, BK=16, 128 threads, 8x8 floats per thread (4 u64-packed),
// grid (8, 8, 8) = 512 CTAs. Reg prefetch + double buffer, one sync/iter.
// Row pads are 16-byte multiples (132, 68) so float4/ulonglong2 SMEM
// accesses stay aligned for every kk.
// ---------------------------------------------------------------------------
__global__ __launch_bounds__(128, 4)
void gemm_v3(const float* __restrict__ A, const float* __restrict__ Wm)
{
    __shared__ __align__(16) float As[2][16][132];
    __shared__ __align__(16) float Ws[2][16][68];

    const int t  = threadIdx.x;
    const int n0 = blockIdx.x * 64;
    const int m0 = blockIdx.y * 128;
    const int kb = blockIdx.z * 256;       // 16 iters of BK=16
    const int rw = t >> 1;                 // W row 0..63
    const int khw = (t & 1) << 3;          // 0 or 8
    const int ty = t >> 3;                 // 0..15 (m groups of 8)
    const int tx = t & 7;                  // 0..7  (n groups of 4+4)

    const float* Ap = A  + (size_t)(m0 + t)  * 2048 + kb;
    const float* Wp = Wm + (size_t)(n0 + rw) * 2048 + kb + khw;

    u64 acc[8][4];
    #pragma unroll
    for (int i = 0; i < 8; ++i)
        #pragma unroll
        for (int j = 0; j < 4; ++j) acc[i][j] = 0ull;

    float4 a0 = *(const float4*)Ap;
    float4 a1 = *(const float4*)(Ap + 4);
    float4 a2 = *(const float4*)(Ap + 8);
    float4 a3 = *(const float4*)(Ap + 12);
    float4 w0 = *(const float4*)Wp;
    float4 w1 = *(const float4*)(Wp + 4);

    #pragma unroll 1
    for (int it = 0; it < 16; ++it) {
        const int buf = it & 1;
        As[buf][ 0][t] = a0.x; As[buf][ 1][t] = a0.y;
        As[buf][ 2][t] = a0.z; As[buf][ 3][t] = a0.w;
        As[buf][ 4][t] = a1.x; As[buf][ 5][t] = a1.y;
        As[buf][ 6][t] = a1.z; As[buf][ 7][t] = a1.w;
        As[buf][ 8][t] = a2.x; As[buf][ 9][t] = a2.y;
        As[buf][10][t] = a2.z; As[buf][11][t] = a2.w;
        As[buf][12][t] = a3.x; As[buf][13][t] = a3.y;
        As[buf][14][t] = a3.z; As[buf][15][t] = a3.w;
        Ws[buf][khw + 0][rw] = w0.x; Ws[buf][khw + 1][rw] = w0.y;
        Ws[buf][khw + 2][rw] = w0.z; Ws[buf][khw + 3][rw] = w0.w;
        Ws[buf][khw + 4][rw] = w1.x; Ws[buf][khw + 5][rw] = w1.y;
        Ws[buf][khw + 6][rw] = w1.z; Ws[buf][khw + 7][rw] = w1.w;

        if (it + 1 < 16) {
            const float* Ap2 = Ap + (it + 1) * 16;
            const float* Wp2 = Wp + (it + 1) * 16;
            a0 = *(const float4*)Ap2;       a1 = *(const float4*)(Ap2 + 4);
            a2 = *(const float4*)(Ap2 + 8); a3 = *(const float4*)(Ap2 + 12);
            w0 = *(const float4*)Wp2;       w1 = *(const float4*)(Wp2 + 4);
        }
        __syncthreads();

        #pragma unroll
        for (int kk = 0; kk < 16; ++kk) {
            float4 af0 = *(const float4*)&As[buf][kk][ty << 3];
            float4 af1 = *(const float4*)&As[buf][kk][(ty << 3) + 4];
            ulonglong2 q0 = *(const ulonglong2*)&Ws[buf][kk][tx << 2];
            ulonglong2 q1 = *(const ulonglong2*)&Ws[buf][kk][32 + (tx << 2)];
            float av[8] = {af0.x, af0.y, af0.z, af0.w, af1.x, af1.y, af1.z, af1.w};
            #pragma unroll
            for (int i = 0; i < 8; ++i) {
                u64 ap = pk2(av[i], av[i]);
                acc[i][0] = fma2(ap, q0.x, acc[i][0]);
                acc[i][1] = fma2(ap, q0.y, acc[i][1]);
                acc[i][2] = fma2(ap, q1.x, acc[i][2]);
                acc[i][3] = fma2(ap, q1.y, acc[i][3]);
            }
        }
        // next iter's STS targets the other buffer; no bottom sync needed
    }

    float* Cp = g_com4[blockIdx.z];
    #pragma unroll
    for (int i = 0; i < 8; ++i) {
        int row = m0 + (ty << 3) + i;
        *(ulonglong2*)&Cp[(size_t)row * 512 + n0 + (tx << 2)] =
            make_ulonglong2(acc[i][0], acc[i][1]);
        *(ulonglong2*)&Cp[(size_t)row * 512 + n0 + 32 + (tx << 2)] =
            make_ulonglong2(acc[i][2], acc[i][3]);
    }
}

// ---------------------------------------------------------------------------
// Quantum circuit v3: 1 CTA (128 threads) per batch row, 32 amps/thread.
// State in SMEM as 2048 elements {Re2, Im2} (each u64 packs two amplitudes
// differing in the spectator bit: bit 11 for A/B layouts, bit 0 for C).
// Element index: A/B layouts -> i[10:0]; C layout -> i[11:1].
// Swizzle E(q) = q ^ ((q>>4)&7).  Wire w <-> bit (11 - w).
// ---------------------------------------------------------------------------
__device__ __forceinline__ int E(int q) { return q ^ ((q >> 4) & 7); }

// Packed complex 2x2 gate over local slot bit LB.
// c[12] splats: p, q, -q, r, s, -s, u, v, -v, w, z, -z  for
// m00=(p,q) m01=(r,s) m10=(u,v) m11=(w,z).
template<int LB>
__device__ __forceinline__ void rotp(u64* Re, u64* Im, const u64* __restrict__ c)
{
    u64 cp = c[0], cq = c[1], cnq = c[2], cr = c[3], cs_ = c[4], cns = c[5];
    u64 cu = c[6], cv = c[7], cnv = c[8], cw = c[9], cz = c[10], cnz = c[11];
    #pragma unroll
    for (int p = 0; p < 8; ++p) {
        int k0 = ((p >> LB) << (LB + 1)) | (p & ((1 << LB) - 1));
        int k1 = k0 | (1 << LB);
        u64 r0 = Re[k0], i0 = Im[k0], r1 = Re[k1], i1 = Im[k1];
        Re[k0] = fma2(cp, r0, fma2(cnq, i0, fma2(cr,  r1, mul2(cns, i1))));
        Im[k0] = fma2(cq, r0, fma2(cp,  i0, fma2(cs_, r1, mul2(cr,  i1))));
        Re[k1] = fma2(cu, r0, fma2(cnv, i0, fma2(cw,  r1, mul2(cnz, i1))));
        Im[k1] = fma2(cv, r0, fma2(cu,  i0, fma2(cz,  r1, mul2(cw,  i1))));
    }
}

// Unscaled Hadamard butterfly on slot bit LB (scale folded into reduction).
template<int LB>
__device__ __forceinline__ void hp(u64* Re, u64* Im, u64 neg1)
{
    #pragma unroll
    for (int p = 0; p < 8; ++p) {
        int k0 = ((p >> LB) << (LB + 1)) | (p & ((1 << LB) - 1));
        int k1 = k0 | (1 << LB);
        u64 r0 = Re[k0], i0 = Im[k0], r1 = Re[k1], i1 = Im[k1];
        Re[k0] = add2(r0, r1); Im[k0] = add2(i0, i1);
        Re[k1] = fma2(neg1, r1, r0); Im[k1] = fma2(neg1, i1, i0);
    }
}

// Net gather index of the 12-CNOT chain with range R (GF(2)-linear).
template<int R>
__device__ __forceinline__ int cnotG(int i)
{
    #pragma unroll
    for (int w = 11; w >= 0; --w) {
        int pc = 11 - w;
        int pt = 11 - ((w + R) % 12);
        i ^= ((i >> pc) & 1) << pt;
    }
    return i;
}

__global__ __launch_bounds__(128, 4)
void circuit_v3(const float* __restrict__ x,    // (1024, 2048) img angles
                const float* __restrict__ bias, // (512,)
                const float* __restrict__ qp,   // (2, 12, 3)
                float* __restrict__ out)        // (1024,)
{
    __shared__ __align__(16) ulonglong2 sm[2048];   // 32 KB state
    __shared__ u64 cf[2][12][12];                   // splatted coefficients
    __shared__ float red[4];

    const int t = threadIdx.x;      // 0..127
    const int b = blockIdx.x;
    const float* img = x + (size_t)b * 2048;
    const size_t crow = (size_t)b * 512;
    float* smf = (float*)sm;

    // --- Rot matrices: Rot = RZ(omega) RY(theta) RZ(phi) ---
    if (t < 24) {
        int l = t / 12, w = t % 12;
        float phi = qp[(l * 12 + w) * 3 + 0];
        float th  = qp[(l * 12 + w) * 3 + 1];
        float om  = qp[(l * 12 + w) * 3 + 2];
        float sh, ch;  sincosf(0.5f * th, &sh, &ch);
        float sa, ca;  sincosf(0.5f * (phi + om), &sa, &ca);
        float sb, cb;  sincosf(0.5f * (phi - om), &sb, &cb);
        float p =  ch * ca, q = -ch * sa;   // m00
        float r = -sh * cb, s = -sh * sb;   // m01
        float u =  sh * cb, v = -sh * sb;   // m10
        float w2 = ch * ca, z =  ch * sa;   // m11
        u64* c = cf[l][w];
        c[0]  = pk2(p, p);   c[1]  = pk2(q, q);   c[2]  = pk2(-q, -q);
        c[3]  = pk2(r, r);   c[4]  = pk2(s, s);   c[5]  = pk2(-s, -s);
        c[6]  = pk2(u, u);   c[7]  = pk2(v, v);   c[8]  = pk2(-v, -v);
        c[9]  = pk2(w2, w2); c[10] = pk2(z, z);   c[11] = pk2(-z, -z);
    }
    __syncthreads();

    const u64 neg1 = pk2(-1.f, -1.f);
    u64 Re[16], Im[16];

    // ===== P1 (A layout: i = spec<<11 | t<<4 | j) : analytic FRQI(com), L0 bits 0-3
    #pragma unroll
    for (int j = 0; j < 16; ++j) {
        if (j & 3) { Re[j] = 0ull; Im[j] = 0ull; }
        else {
            int j9 = (t << 2) | (j >> 2);
            int aidx = __brev((unsigned)j9) >> 23;
            float comv = bias[aidx];
            #pragma unroll
            for (int s = 0; s < SPLITK; ++s) comv += g_com4[s][crow + aidx];
            float sn, cs; __sincosf(0.5f * comv, &sn, &cs);
            Re[j] = pk2(cs * 0.04419417382415922f, sn * 0.04419417382415922f);
            Im[j] = 0ull;
        }
    }
    rotp<0>(Re, Im, cf[0][11]); rotp<1>(Re, Im, cf[0][10]);
    rotp<2>(Re, Im, cf[0][9]);  rotp<3>(Re, Im, cf[0][8]);
    #pragma unroll
    for (int j = 0; j < 16; ++j) sm[E((t << 4) | j)] = make_ulonglong2(Re[j], Im[j]);
    __syncthreads();

    // ===== P2 (B layout: q = t[6:4]<<8 | j<<4 | t[3:0]) : L0 bits 4-7
    {
        const int pb = ((t >> 4) << 8) | (t & 15);
        #pragma unroll
        for (int j = 0; j < 16; ++j) {
            ulonglong2 e = sm[E(pb | (j << 4))];
            Re[j] = e.x; Im[j] = e.y;
        }
        rotp<0>(Re, Im, cf[0][7]); rotp<1>(Re, Im, cf[0][6]);
        rotp<2>(Re, Im, cf[0][5]); rotp<3>(Re, Im, cf[0][4]);
        __syncthreads();
        // scatter-store into C layout (pairs over bit 0)
        const int qbase = ((t >> 4) << 7) | ((t >> 1) & 7);
        const int half = t & 1;
        #pragma unroll
        for (int j = 0; j < 16; ++j) {
            float rl, rh, il, ih;
            unpk2(rl, rh, Re[j]); unpk2(il, ih, Im[j]);
            int f0 = E(qbase | (j << 3)) * 4 + half;
            int f1 = E(qbase | (j << 3) | 1024) * 4 + half;
            smf[f0] = rl; smf[f0 + 2] = il;
            smf[f1] = rh; smf[f1 + 2] = ih;
        }
    }
    __syncthreads();

    // ===== P3 (C layout: q = j<<7 | t) : L0 bits 8-11
    #pragma unroll
    for (int j = 0; j < 16; ++j) {
        ulonglong2 e = sm[E((j << 7) | t)];
        Re[j] = e.x; Im[j] = e.y;
    }
    rotp<0>(Re, Im, cf[0][3]); rotp<1>(Re, Im, cf[0][2]);
    rotp<2>(Re, Im, cf[0][1]); rotp<3>(Re, Im, cf[0][0]);
    #pragma unroll
    for (int j = 0; j < 16; ++j) sm[E((j << 7) | t)] = make_ulonglong2(Re[j], Im[j]);
    __syncthreads();

    // ===== P4 (A) : CNOT r=1 gather from C storage, L1 bits 0-3
    {
        int Gb = cnotG<1>(t << 4);
        int g0 = cnotG<1>(1), g1 = cnotG<1>(2), g2 = cnotG<1>(4), g3 = cnotG<1>(8);
        int gS = cnotG<1>(2048);
        #pragma unroll
        for (int j = 0; j < 16; ++j) {
            int o0 = Gb ^ ((j & 1) ? g0 : 0) ^ ((j & 2) ? g1 : 0)
                        ^ ((j & 4) ? g2 : 0) ^ ((j & 8) ? g3 : 0);
            int o1 = o0 ^ gS;
            int f0 = E(o0 >> 1) * 4 + (o0 & 1);
            int f1 = E(o1 >> 1) * 4 + (o1 & 1);
            Re[j] = pk2(smf[f0], smf[f1]);
            Im[j] = pk2(smf[f0 + 2], smf[f1 + 2]);
        }
    }
    __syncthreads();
    rotp<0>(Re, Im, cf[1][11]); rotp<1>(Re, Im, cf[1][10]);
    rotp<2>(Re, Im, cf[1][9]);  rotp<3>(Re, Im, cf[1][8]);
    #pragma unroll
    for (int j = 0; j < 16; ++j) sm[E((t << 4) | j)] = make_ulonglong2(Re[j], Im[j]);
    __syncthreads();

    // ===== P5 (B) : L1 bits 4-7, scatter-store to C
    {
        const int pb = ((t >> 4) << 8) | (t & 15);
        #pragma unroll
        for (int j = 0; j < 16; ++j) {
            ulonglong2 e = sm[E(pb | (j << 4))];
            Re[j] = e.x; Im[j] = e.y;
        }
        rotp<0>(Re, Im, cf[1][7]); rotp<1>(Re, Im, cf[1][6]);
        rotp<2>(Re, Im, cf[1][5]); rotp<3>(Re, Im, cf[1][4]);
        __syncthreads();
        const int qbase = ((t >> 4) << 7) | ((t >> 1) & 7);
        const int half = t & 1;
        #pragma unroll
        for (int j = 0; j < 16; ++j) {
            float rl, rh, il, ih;
            unpk2(rl, rh, Re[j]); unpk2(il, ih, Im[j]);
            int f0 = E(qbase | (j << 3)) * 4 + half;
            int f1 = E(qbase | (j << 3) | 1024) * 4 + half;
            smf[f0] = rl; smf[f0 + 2] = il;
            smf[f1] = rh; smf[f1 + 2] = ih;
        }
    }
    __syncthreads();

    // ===== P6 (C) : L1 bits 8-11
    #pragma unroll
    for (int j = 0; j < 16; ++j) {
        ulonglong2 e = sm[E((j << 7) | t)];
        Re[j] = e.x; Im[j] = e.y;
    }
    rotp<0>(Re, Im, cf[1][3]); rotp<1>(Re, Im, cf[1][2]);
    rotp<2>(Re, Im, cf[1][1]); rotp<3>(Re, Im, cf[1][0]);
    #pragma unroll
    for (int j = 0; j < 16; ++j) sm[E((j << 7) | t)] = make_ulonglong2(Re[j], Im[j]);
    __syncthreads();

    // ===== P7 (A) : CNOT r=2 gather from C storage, H bits 0-3
    {
        int Gb = cnotG<2>(t << 4);
        int g0 = cnotG<2>(1), g1 = cnotG<2>(2), g2 = cnotG<2>(4), g3 = cnotG<2>(8);
        int gS = cnotG<2>(2048);
        #pragma unroll
        for (int j = 0; j < 16; ++j) {
            int o0 = Gb ^ ((j & 1) ? g0 : 0) ^ ((j & 2) ? g1 : 0)
                        ^ ((j & 4) ? g2 : 0) ^ ((j & 8) ? g3 : 0);
            int o1 = o0 ^ gS;
            int f0 = E(o0 >> 1) * 4 + (o0 & 1);
            int f1 = E(o1 >> 1) * 4 + (o1 & 1);
            Re[j] = pk2(smf[f0], smf[f1]);
            Im[j] = pk2(smf[f0 + 2], smf[f1 + 2]);
        }
    }
    __syncthreads();
    hp<0>(Re, Im, neg1); hp<1>(Re, Im, neg1); hp<2>(Re, Im, neg1); hp<3>(Re, Im, neg1);
    #pragma unroll
    for (int j = 0; j < 16; ++j) sm[E((t << 4) | j)] = make_ulonglong2(Re[j], Im[j]);
    __syncthreads();

    // ===== P8 (B) : H bits 4-7, scatter-store to C
    {
        const int pb = ((t >> 4) << 8) | (t & 15);
        #pragma unroll
        for (int j = 0; j < 16; ++j) {
            ulonglong2 e = sm[E(pb | (j << 4))];
            Re[j] = e.x; Im[j] = e.y;
        }
        hp<0>(Re, Im, neg1); hp<1>(Re, Im, neg1); hp<2>(Re, Im, neg1); hp<3>(Re, Im, neg1);
        __syncthreads();
        const int qbase = ((t >> 4) << 7) | ((t >> 1) & 7);
        const int half = t & 1;
        #pragma unroll
        for (int j = 0; j < 16; ++j) {
            float rl, rh, il, ih;
            unpk2(rl, rh, Re[j]); unpk2(il, ih, Im[j]);
            int f0 = E(qbase | (j << 3)) * 4 + half;
            int f1 = E(qbase | (j << 3) | 1024) * 4 + half;
            smf[f0] = rl; smf[f0 + 2] = il;
            smf[f1] = rh; smf[f1 + 2] = ih;
        }
    }
    __syncthreads();

    // ===== P9 (C) : H bits 8-10, UC-RY(img) on bit 11, measure
    #pragma unroll
    for (int j = 0; j < 16; ++j) {
        ulonglong2 e = sm[E((j << 7) | t)];
        Re[j] = e.x; Im[j] = e.y;
    }
    hp<0>(Re, Im, neg1); hp<1>(Re, Im, neg1); hp<2>(Re, Im, neg1);

    #pragma unroll
    for (int jj = 0; jj < 8; ++jj) {
        int a0 = __brev((unsigned)((jj << 8) | (t << 1))) >> 21;
        float s0, c0, s1, c1;
        __sincosf(0.5f * img[a0], &s0, &c0);
        __sincosf(0.5f * img[a0 | 1024], &s1, &c1);
        u64 cs2 = pk2(c0, c1), sn2 = pk2(s0, s1), nsn2 = pk2(-s0, -s1);
        u64 Ra = Re[jj], Ia = Im[jj], Rb = Re[jj + 8], Ib = Im[jj + 8];
        Re[jj]     = fma2(cs2, Ra, mul2(nsn2, Rb));
        Im[jj]     = fma2(cs2, Ia, mul2(nsn2, Ib));
        Re[jj + 8] = fma2(sn2, Ra, mul2(cs2, Rb));
        Im[jj + 8] = fma2(sn2, Ia, mul2(cs2, Ib));
    }

    u64 accN = 0ull, accP = 0ull;
    #pragma unroll
    for (int j = 0; j < 8; ++j) {
        accN = fma2(Re[j], Re[j], accN);
        accN = fma2(Im[j], Im[j], accN);
    }
    #pragma unroll
    for (int j = 8; j < 16; ++j) {
        accP = fma2(Re[j], Re[j], accP);
        accP = fma2(Im[j], Im[j], accP);
    }
    float pl, ph, nl, nh;
    unpk2(pl, ph, accP); unpk2(nl, nh, accN);
    float acc = (pl + ph) - (nl + nh);

    #pragma unroll
    for (int o = 16; o; o >>= 1) acc += __shfl_xor_sync(0xffffffffu, acc, o);
    if ((t & 31) == 0) red[t >> 5] = acc;
    __syncthreads();
    if (t == 0)
        out[b] = (red[0] + red[1] + red[2] + red[3]) * (1.0f / 2048.0f);
}

// ---------------------------------------------------------------------------
extern "C" void kernel_launch(void* const* d_in, const int* in_sizes, int n_in,
                              void* d_out, int out_size)
{
    const float* x  = (const float*)d_in[0];   // (1024, 2, 32, 32) -> (1024, 2048)
    const float* Wm = (const float*)d_in[1];   // (512, 2048)
    const float* bb = (const float*)d_in[2];   // (512,)
    const float* qp = (const float*)d_in[3];   // (2, 12, 3)
    float* out = (float*)d_out;                // (1024,)

    dim3 gemm_grid(512 / 64, 1024 / 128, SPLITK);   // (8, 8, 8) = 512 CTAs
    gemm_v3<<<gemm_grid, 128>>>(x, Wm);
    circuit_v3<<<1024, 128>>>(x, bb, qp, out);
}

// round 9
// speedup vs baseline: 1.1194x; 1.1194x over previous
#include <cuda_runtime.h>
#include <math.h>

typedef unsigned long long u64;

#define SPLITK 4

// Split-K partial sums of x @ W^T (bias added in circuit kernel). No allocs.
__device__ float g_com4[SPLITK][1024 * 512];

// ---------------------------------------------------------------------------
// Packed fp32x2 helpers (PTX-only)
// ---------------------------------------------------------------------------
__device__ __forceinline__ u64 pk2(float lo, float hi) {
    u64 d; asm("mov.b64 %0, {%1, %2};" : "=l"(d) : "f"(lo), "f"(hi)); return d;
}
__device__ __forceinline__ u64 fma2(u64 a, u64 b, u64 c) {
    u64 d; asm("fma.rn.f32x2 %0, %1, %2, %3;" : "=l"(d) : "l"(a), "l"(b), "l"(c)); return d;
}
__device__ __forceinline__ u64 mul2(u64 a, u64 b) {
    u64 d; asm("mul.rn.f32x2 %0, %1, %2;" : "=l"(d) : "l"(a), "l"(b)); return d;
}
__device__ __forceinline__ u64 add2(u64 a, u64 b) {
    u64 d; asm("add.rn.f32x2 %0, %1, %2;" : "=l"(d) : "l"(a), "l"(b)); return d;
}
__device__ __forceinline__ void unpk2(float& lo, float& hi, u64 d) {
    asm("mov.b64 {%0, %1}, %2;" : "=f"(lo), "=f"(hi) : "l"(d));
}

// ---------------------------------------------------------------------------
// GEMM (R5-proven): split-K partials of x @ W^T.
// M=1024, N=512, K=2048, SPLITK=4 (512 K per CTA).
// BM=BN=128, BK=16, 256 threads, 8x8 per thread, f32x2 accumulators.
// ---------------------------------------------------------------------------
__global__ __launch_bounds__(256)
void gemm_v2(const float* __restrict__ A, const float* __restrict__ Wm)
{
    __shared__ __align__(16) float As[2][16][132];
    __shared__ __align__(16) float Ws[2][16][132];

    const int tid = threadIdx.x;
    const int n0 = blockIdx.x * 128;
    const int m0 = blockIdx.y * 128;
    const int kb = blockIdx.z * 512;
    const int r  = tid >> 1;
    const int kh = (tid & 1) << 3;
    const int ty = tid >> 4;
    const int tx = tid & 15;

    const float* Ap = A  + (size_t)(m0 + r) * 2048 + kb + kh;
    const float* Wp = Wm + (size_t)(n0 + r) * 2048 + kb + kh;

    u64 acc[8][4];
    #pragma unroll
    for (int i = 0; i < 8; ++i)
        #pragma unroll
        for (int j = 0; j < 4; ++j) acc[i][j] = 0ull;

    float4 a0 = *(const float4*)Ap;
    float4 a1 = *(const float4*)(Ap + 4);
    float4 w0 = *(const float4*)Wp;
    float4 w1 = *(const float4*)(Wp + 4);

    #pragma unroll 1
    for (int it = 0; it < 32; ++it) {
        const int buf = it & 1;
        As[buf][kh + 0][r] = a0.x; As[buf][kh + 1][r] = a0.y;
        As[buf][kh + 2][r] = a0.z; As[buf][kh + 3][r] = a0.w;
        As[buf][kh + 4][r] = a1.x; As[buf][kh + 5][r] = a1.y;
        As[buf][kh + 6][r] = a1.z; As[buf][kh + 7][r] = a1.w;
        Ws[buf][kh + 0][r] = w0.x; Ws[buf][kh + 1][r] = w0.y;
        Ws[buf][kh + 2][r] = w0.z; Ws[buf][kh + 3][r] = w0.w;
        Ws[buf][kh + 4][r] = w1.x; Ws[buf][kh + 5][r] = w1.y;
        Ws[buf][kh + 6][r] = w1.z; Ws[buf][kh + 7][r] = w1.w;

        if (it + 1 < 32) {
            const float* Ap2 = Ap + (it + 1) * 16;
            const float* Wp2 = Wp + (it + 1) * 16;
            a0 = *(const float4*)Ap2; a1 = *(const float4*)(Ap2 + 4);
            w0 = *(const float4*)Wp2; w1 = *(const float4*)(Wp2 + 4);
        }
        __syncthreads();

        #pragma unroll
        for (int kk = 0; kk < 16; ++kk) {
            float4 af0 = *(const float4*)&As[buf][kk][ty << 3];
            float4 af1 = *(const float4*)&As[buf][kk][(ty << 3) + 4];
            ulonglong2 q0 = *(const ulonglong2*)&Ws[buf][kk][tx << 2];
            ulonglong2 q1 = *(const ulonglong2*)&Ws[buf][kk][64 + (tx << 2)];
            float av[8] = {af0.x, af0.y, af0.z, af0.w, af1.x, af1.y, af1.z, af1.w};
            #pragma unroll
            for (int i = 0; i < 8; ++i) {
                u64 ap = pk2(av[i], av[i]);
                acc[i][0] = fma2(ap, q0.x, acc[i][0]);
                acc[i][1] = fma2(ap, q0.y, acc[i][1]);
                acc[i][2] = fma2(ap, q1.x, acc[i][2]);
                acc[i][3] = fma2(ap, q1.y, acc[i][3]);
            }
        }
    }

    float* Cp = g_com4[blockIdx.z];
    #pragma unroll
    for (int i = 0; i < 8; ++i) {
        int row = m0 + (ty << 3) + i;
        *(ulonglong2*)&Cp[(size_t)row * 512 + n0 + (tx << 2)] =
            make_ulonglong2(acc[i][0], acc[i][1]);
        *(ulonglong2*)&Cp[(size_t)row * 512 + n0 + 64 + (tx << 2)] =
            make_ulonglong2(acc[i][2], acc[i][3]);
    }
}

// ---------------------------------------------------------------------------
// Quantum circuit v4: 1 CTA (256 threads) simulates TWO batch rows (b, b+512).
// Each state element = {Re2, Im2}: u64 halves hold (row0, row1) — the batch
// index is a spectator for every gate, so indexing is exactly v2's:
// full 12-bit amp index i, swizzle swz(i) = i ^ ((i>>4)&0xF), wire w <-> bit 11-w.
// Gates are pure FFMA2 (SoA re/im, negations folded into splatted coeffs).
// ---------------------------------------------------------------------------
__device__ __forceinline__ int swz(int i) { return i ^ ((i >> 4) & 0xF); }

// Packed complex 2x2 gate over local slot bit LB.
// c[12] splats: p, q, -q, r, s, -s, u, v, -v, w, z, -z  for
// m00=(p,q) m01=(r,s) m10=(u,v) m11=(w,z).
template<int LB>
__device__ __forceinline__ void rotp(u64* Re, u64* Im, const u64* __restrict__ c)
{
    u64 cp = c[0], cq = c[1], cnq = c[2], cr = c[3], cs_ = c[4], cns = c[5];
    u64 cu = c[6], cv = c[7], cnv = c[8], cw = c[9], cz = c[10], cnz = c[11];
    #pragma unroll
    for (int p = 0; p < 8; ++p) {
        int k0 = ((p >> LB) << (LB + 1)) | (p & ((1 << LB) - 1));
        int k1 = k0 | (1 << LB);
        u64 r0 = Re[k0], i0 = Im[k0], r1 = Re[k1], i1 = Im[k1];
        Re[k0] = fma2(cp, r0, fma2(cnq, i0, fma2(cr,  r1, mul2(cns, i1))));
        Im[k0] = fma2(cq, r0, fma2(cp,  i0, fma2(cs_, r1, mul2(cr,  i1))));
        Re[k1] = fma2(cu, r0, fma2(cnv, i0, fma2(cw,  r1, mul2(cnz, i1))));
        Im[k1] = fma2(cv, r0, fma2(cu,  i0, fma2(cz,  r1, mul2(cw,  i1))));
    }
}

// Unscaled Hadamard butterfly on slot bit LB (scale folded into reduction).
template<int LB>
__device__ __forceinline__ void hp(u64* Re, u64* Im, u64 neg1)
{
    #pragma unroll
    for (int p = 0; p < 8; ++p) {
        int k0 = ((p >> LB) << (LB + 1)) | (p & ((1 << LB) - 1));
        int k1 = k0 | (1 << LB);
        u64 r0 = Re[k0], i0 = Im[k0], r1 = Re[k1], i1 = Im[k1];
        Re[k0] = add2(r0, r1); Im[k0] = add2(i0, i1);
        Re[k1] = fma2(neg1, r1, r0); Im[k1] = fma2(neg1, i1, i0);
    }
}

// Net gather index of the 12-CNOT chain with range R (GF(2)-linear).
template<int R>
__device__ __forceinline__ int cnotG(int i)
{
    #pragma unroll
    for (int w = 11; w >= 0; --w) {
        int pc = 11 - w;
        int pt = 11 - ((w + R) % 12);
        i ^= ((i >> pc) & 1) << pt;
    }
    return i;
}

__global__ __launch_bounds__(256, 2)
void circuit_v4(const float* __restrict__ x,    // (1024, 2048) img angles
                const float* __restrict__ bias, // (512,)
                const float* __restrict__ qp,   // (2, 12, 3)
                float* __restrict__ out)        // (1024,)
{
    extern __shared__ __align__(16) ulonglong2 st[];   // 4096 elems = 64 KB
    __shared__ u64 cf[2][12][12];
    __shared__ u64 red[8];

    const int t  = threadIdx.x;       // 0..255
    const int b0 = blockIdx.x;        // rows b0 and b0+512
    const float* img0 = x + (size_t)b0 * 2048;
    const float* img1 = x + ((size_t)b0 + 512) * 2048;
    const size_t c0off = (size_t)b0 * 512;
    const size_t c1off = ((size_t)b0 + 512) * 512;

    // --- Rot matrices: Rot = RZ(omega) RY(theta) RZ(phi), splatted ---
    if (t < 24) {
        int l = t / 12, w = t % 12;
        float phi = qp[(l * 12 + w) * 3 + 0];
        float th  = qp[(l * 12 + w) * 3 + 1];
        float om  = qp[(l * 12 + w) * 3 + 2];
        float sh, ch;  sincosf(0.5f * th, &sh, &ch);
        float sa, ca;  sincosf(0.5f * (phi + om), &sa, &ca);
        float sb, cb;  sincosf(0.5f * (phi - om), &sb, &cb);
        float p =  ch * ca, q = -ch * sa;   // m00
        float r = -sh * cb, s = -sh * sb;   // m01
        float u =  sh * cb, v = -sh * sb;   // m10
        float w2 = ch * ca, z =  ch * sa;   // m11
        u64* c = cf[l][w];
        c[0]  = pk2(p, p);   c[1]  = pk2(q, q);   c[2]  = pk2(-q, -q);
        c[3]  = pk2(r, r);   c[4]  = pk2(s, s);   c[5]  = pk2(-s, -s);
        c[6]  = pk2(u, u);   c[7]  = pk2(v, v);   c[8]  = pk2(-v, -v);
        c[9]  = pk2(w2, w2); c[10] = pk2(z, z);   c[11] = pk2(-z, -z);
    }
    __syncthreads();

    const u64 neg1 = pk2(-1.f, -1.f);
    u64 Re[16], Im[16];

    // ===== P1 (A: i = t<<4 | j) : analytic FRQI(com) for both rows, L0 bits 0-3
    #pragma unroll
    for (int j = 0; j < 16; ++j) {
        int i = (t << 4) | j;
        if (i & 3) { Re[j] = 0ull; Im[j] = 0ull; }
        else {
            int aidx = __brev((unsigned)((i >> 2) & 511)) >> 23;
            float cv0 = bias[aidx], cv1 = cv0;
            #pragma unroll
            for (int s = 0; s < SPLITK; ++s) {
                cv0 += g_com4[s][c0off + aidx];
                cv1 += g_com4[s][c1off + aidx];
            }
            float s0, q0, s1, q1;
            __sincosf(0.5f * cv0, &s0, &q0);
            __sincosf(0.5f * cv1, &s1, &q1);
            float a0 = ((i >> 11) & 1) ? s0 : q0;
            float a1 = ((i >> 11) & 1) ? s1 : q1;
            Re[j] = pk2(a0 * 0.04419417382415922f, a1 * 0.04419417382415922f);
            Im[j] = 0ull;
        }
    }
    rotp<0>(Re, Im, cf[0][11]); rotp<1>(Re, Im, cf[0][10]);
    rotp<2>(Re, Im, cf[0][9]);  rotp<3>(Re, Im, cf[0][8]);
    #pragma unroll
    for (int j = 0; j < 16; ++j) st[swz((t << 4) | j)] = make_ulonglong2(Re[j], Im[j]);
    __syncthreads();

    // ===== P2 (B: i = t[7:4]<<8 | j<<4 | t[3:0]) : L0 bits 4-7
    {
        const int pb = ((t >> 4) << 8) | (t & 15);
        #pragma unroll
        for (int j = 0; j < 16; ++j) {
            ulonglong2 e = st[swz(pb | (j << 4))];
            Re[j] = e.x; Im[j] = e.y;
        }
        rotp<0>(Re, Im, cf[0][7]); rotp<1>(Re, Im, cf[0][6]);
        rotp<2>(Re, Im, cf[0][5]); rotp<3>(Re, Im, cf[0][4]);
        #pragma unroll
        for (int j = 0; j < 16; ++j) st[swz(pb | (j << 4))] = make_ulonglong2(Re[j], Im[j]);
    }
    __syncthreads();

    // ===== P3 (C: i = j<<8 | t) : L0 bits 8-11
    #pragma unroll
    for (int j = 0; j < 16; ++j) {
        ulonglong2 e = st[swz((j << 8) | t)];
        Re[j] = e.x; Im[j] = e.y;
    }
    rotp<0>(Re, Im, cf[0][3]); rotp<1>(Re, Im, cf[0][2]);
    rotp<2>(Re, Im, cf[0][1]); rotp<3>(Re, Im, cf[0][0]);
    #pragma unroll
    for (int j = 0; j < 16; ++j) st[swz((j << 8) | t)] = make_ulonglong2(Re[j], Im[j]);
    __syncthreads();

    // ===== P4 (A) : CNOT r=1 folded gather, L1 bits 0-3
    {
        int Gb = cnotG<1>(t << 4);
        int g0 = cnotG<1>(1), g1 = cnotG<1>(2), g2 = cnotG<1>(4), g3 = cnotG<1>(8);
        #pragma unroll
        for (int j = 0; j < 16; ++j) {
            int gi = Gb ^ ((j & 1) ? g0 : 0) ^ ((j & 2) ? g1 : 0)
                        ^ ((j & 4) ? g2 : 0) ^ ((j & 8) ? g3 : 0);
            ulonglong2 e = st[swz(gi)];
            Re[j] = e.x; Im[j] = e.y;
        }
    }
    __syncthreads();   // all gathered reads done before in-place writes
    rotp<0>(Re, Im, cf[1][11]); rotp<1>(Re, Im, cf[1][10]);
    rotp<2>(Re, Im, cf[1][9]);  rotp<3>(Re, Im, cf[1][8]);
    #pragma unroll
    for (int j = 0; j < 16; ++j) st[swz((t << 4) | j)] = make_ulonglong2(Re[j], Im[j]);
    __syncthreads();

    // ===== P5 (B) : L1 bits 4-7
    {
        const int pb = ((t >> 4) << 8) | (t & 15);
        #pragma unroll
        for (int j = 0; j < 16; ++j) {
            ulonglong2 e = st[swz(pb | (j << 4))];
            Re[j] = e.x; Im[j] = e.y;
        }
        rotp<0>(Re, Im, cf[1][7]); rotp<1>(Re, Im, cf[1][6]);
        rotp<2>(Re, Im, cf[1][5]); rotp<3>(Re, Im, cf[1][4]);
        #pragma unroll
        for (int j = 0; j < 16; ++j) st[swz(pb | (j << 4))] = make_ulonglong2(Re[j], Im[j]);
    }
    __syncthreads();

    // ===== P6 (C) : L1 bits 8-11
    #pragma unroll
    for (int j = 0; j < 16; ++j) {
        ulonglong2 e = st[swz((j << 8) | t)];
        Re[j] = e.x; Im[j] = e.y;
    }
    rotp<0>(Re, Im, cf[1][3]); rotp<1>(Re, Im, cf[1][2]);
    rotp<2>(Re, Im, cf[1][1]); rotp<3>(Re, Im, cf[1][0]);
    #pragma unroll
    for (int j = 0; j < 16; ++j) st[swz((j << 8) | t)] = make_ulonglong2(Re[j], Im[j]);
    __syncthreads();

    // ===== P7 (A) : CNOT r=2 folded gather, H bits 0-3
    {
        int Gb = cnotG<2>(t << 4);
        int g0 = cnotG<2>(1), g1 = cnotG<2>(2), g2 = cnotG<2>(4), g3 = cnotG<2>(8);
        #pragma unroll
        for (int j = 0; j < 16; ++j) {
            int gi = Gb ^ ((j & 1) ? g0 : 0) ^ ((j & 2) ? g1 : 0)
                        ^ ((j & 4) ? g2 : 0) ^ ((j & 8) ? g3 : 0);
            ulonglong2 e = st[swz(gi)];
            Re[j] = e.x; Im[j] = e.y;
        }
    }
    __syncthreads();
    hp<0>(Re, Im, neg1); hp<1>(Re, Im, neg1); hp<2>(Re, Im, neg1); hp<3>(Re, Im, neg1);
    #pragma unroll
    for (int j = 0; j < 16; ++j) st[swz((t << 4) | j)] = make_ulonglong2(Re[j], Im[j]);
    __syncthreads();

    // ===== P8 (B) : H bits 4-7
    {
        const int pb = ((t >> 4) << 8) | (t & 15);
        #pragma unroll
        for (int j = 0; j < 16; ++j) {
            ulonglong2 e = st[swz(pb | (j << 4))];
            Re[j] = e.x; Im[j] = e.y;
        }
        hp<0>(Re, Im, neg1); hp<1>(Re, Im, neg1); hp<2>(Re, Im, neg1); hp<3>(Re, Im, neg1);
        #pragma unroll
        for (int j = 0; j < 16; ++j) st[swz(pb | (j << 4))] = make_ulonglong2(Re[j], Im[j]);
    }
    __syncthreads();

    // ===== P9 (C) : H bits 8-10, UC-RY(img) on bit 11 for both rows, measure
    #pragma unroll
    for (int j = 0; j < 16; ++j) {
        ulonglong2 e = st[swz((j << 8) | t)];
        Re[j] = e.x; Im[j] = e.y;
    }
    hp<0>(Re, Im, neg1); hp<1>(Re, Im, neg1); hp<2>(Re, Im, neg1);

    #pragma unroll
    for (int k = 0; k < 8; ++k) {
        int i0 = (k << 8) | t;                          // bit 11 = 0
        int aidx = __brev((unsigned)i0) >> 21;          // 11-bit reversal
        float s0, q0, s1, q1;
        __sincosf(0.5f * img0[aidx], &s0, &q0);
        __sincosf(0.5f * img1[aidx], &s1, &q1);
        u64 cs2 = pk2(q0, q1), sn2 = pk2(s0, s1), nsn2 = pk2(-s0, -s1);
        u64 Ra = Re[k], Ia = Im[k], Rb = Re[k + 8], Ib = Im[k + 8];
        Re[k]     = fma2(cs2, Ra, mul2(nsn2, Rb));
        Im[k]     = fma2(cs2, Ia, mul2(nsn2, Ib));
        Re[k + 8] = fma2(sn2, Ra, mul2(cs2, Rb));
        Im[k + 8] = fma2(sn2, Ia, mul2(cs2, Ib));
    }

    u64 accN = 0ull, accP = 0ull;
    #pragma unroll
    for (int k = 0; k < 8; ++k) {
        accN = fma2(Re[k], Re[k], accN);
        accN = fma2(Im[k], Im[k], accN);
    }
    #pragma unroll
    for (int k = 8; k < 16; ++k) {
        accP = fma2(Re[k], Re[k], accP);
        accP = fma2(Im[k], Im[k], accP);
    }
    u64 acc = fma2(neg1, accN, accP);   // (p1 - p0) packed for both rows

    #pragma unroll
    for (int o = 16; o; o >>= 1)
        acc = add2(acc, __shfl_xor_sync(0xffffffffu, acc, o));
    if ((t & 31) == 0) red[t >> 5] = acc;
    __syncthreads();
    if (t == 0) {
        u64 s = red[0];
        #pragma unroll
        for (int w = 1; w < 8; ++w) s = add2(s, red[w]);
        float lo, hi; unpk2(lo, hi, s);
        out[b0]       = lo * (1.0f / 2048.0f);
        out[b0 + 512] = hi * (1.0f / 2048.0f);
    }
}

// ---------------------------------------------------------------------------
extern "C" void kernel_launch(void* const* d_in, const int* in_sizes, int n_in,
                              void* d_out, int out_size)
{
    const float* x  = (const float*)d_in[0];   // (1024, 2, 32, 32) -> (1024, 2048)
    const float* Wm = (const float*)d_in[1];   // (512, 2048)
    const float* bb = (const float*)d_in[2];   // (512,)
    const float* qp = (const float*)d_in[3];   // (2, 12, 3)
    float* out = (float*)d_out;                // (1024,)

    cudaFuncSetAttribute(circuit_v4,
                         cudaFuncAttributeMaxDynamicSharedMemorySize, 65536);

    dim3 gemm_grid(512 / 128, 1024 / 128, SPLITK);   // (4, 8, 4) = 128 CTAs
    gemm_v2<<<gemm_grid, 256>>>(x, Wm);
    circuit_v4<<<512, 256, 65536>>>(x, bb, qp, out);
}

// round 10
// speedup vs baseline: 1.3002x; 1.1615x over previous
#include <cuda_runtime.h>
#include <math.h>

typedef unsigned long long u64;
typedef unsigned int u32;

#define SPLITK 4

// Split-K partial sums of x @ W^T (bias added in circuit kernel). No allocs.
__device__ float g_com4[SPLITK][1024 * 512];

// ---------------------------------------------------------------------------
// Packed fp32x2 helpers (PTX-only)
// ---------------------------------------------------------------------------
__device__ __forceinline__ u64 pk2(float lo, float hi) {
    u64 d; asm("mov.b64 %0, {%1, %2};" : "=l"(d) : "f"(lo), "f"(hi)); return d;
}
__device__ __forceinline__ u64 fma2(u64 a, u64 b, u64 c) {
    u64 d; asm("fma.rn.f32x2 %0, %1, %2, %3;" : "=l"(d) : "l"(a), "l"(b), "l"(c)); return d;
}
__device__ __forceinline__ u64 mul2(u64 a, u64 b) {
    u64 d; asm("mul.rn.f32x2 %0, %1, %2;" : "=l"(d) : "l"(a), "l"(b)); return d;
}
__device__ __forceinline__ u64 add2(u64 a, u64 b) {
    u64 d; asm("add.rn.f32x2 %0, %1, %2;" : "=l"(d) : "l"(a), "l"(b)); return d;
}
__device__ __forceinline__ void unpk2(float& lo, float& hi, u64 d) {
    asm("mov.b64 {%0, %1}, %2;" : "=f"(lo), "=f"(hi) : "l"(d));
}
// swap halves: (x, y) -> (y, x)
__device__ __forceinline__ u64 hswap(u64 a) {
    float lo, hi; unpk2(lo, hi, a);
    return pk2(hi, lo);
}
// round-to-nearest tf32 conversion
__device__ __forceinline__ u32 tf32c(float a) {
    u32 r; asm("cvt.rna.tf32.f32 %0, %1;" : "=r"(r) : "f"(a)); return r;
}

// ---------------------------------------------------------------------------
// GEMM-TC: split-K partials of x @ W^T via mma.sync m16n8k8 tf32.
// BM=128, BN=64, BK=16, 256 threads = 8 warps, warp tile 64x16 (2m x 4n grid).
// grid (8, 8, 4) = 256 CTAs, K/CTA = 512 -> 32 iters.
// Smem k-major: As[k][136], Ws[k][72] -- pads make all frag LDS.32 patterns
// (8*kc + m') conflict-free.
// ---------------------------------------------------------------------------
__global__ __launch_bounds__(256)
void gemm_tc(const float* __restrict__ A, const float* __restrict__ Wm)
{
    __shared__ __align__(16) float As[2][16][136];
    __shared__ __align__(16) float Ws[2][16][72];

    const int t  = threadIdx.x;
    const int n0 = blockIdx.x * 64;
    const int m0 = blockIdx.y * 128;
    const int kb = blockIdx.z * 512;

    // loader mapping
    const int ra  = t >> 1;            // A row 0..127
    const int kha = (t & 1) << 3;      // 0 or 8
    const int rw  = t >> 2;            // W row 0..63
    const int khw = (t & 3) << 2;      // 0,4,8,12

    const float* Ap = A  + (size_t)(m0 + ra) * 2048 + kb + kha;
    const float* Wp = Wm + (size_t)(n0 + rw) * 2048 + kb + khw;

    // mma mapping
    const int lane = t & 31;
    const int wid  = t >> 5;
    const int wm   = wid >> 2;         // 0..1  (m half)
    const int wn   = wid & 3;          // 0..3  (n quarter)
    const int mr   = lane >> 2;        // 0..7
    const int kc   = lane & 3;         // 0..3

    float acc[4][2][4];
    #pragma unroll
    for (int mt = 0; mt < 4; ++mt)
        #pragma unroll
        for (int nt = 0; nt < 2; ++nt)
            #pragma unroll
            for (int i = 0; i < 4; ++i) acc[mt][nt][i] = 0.f;

    float4 pa0 = *(const float4*)Ap;
    float4 pa1 = *(const float4*)(Ap + 4);
    float4 pw0 = *(const float4*)Wp;

    #pragma unroll 1
    for (int it = 0; it < 32; ++it) {
        const int buf = it & 1;
        As[buf][kha + 0][ra] = pa0.x; As[buf][kha + 1][ra] = pa0.y;
        As[buf][kha + 2][ra] = pa0.z; As[buf][kha + 3][ra] = pa0.w;
        As[buf][kha + 4][ra] = pa1.x; As[buf][kha + 5][ra] = pa1.y;
        As[buf][kha + 6][ra] = pa1.z; As[buf][kha + 7][ra] = pa1.w;
        Ws[buf][khw + 0][rw] = pw0.x; Ws[buf][khw + 1][rw] = pw0.y;
        Ws[buf][khw + 2][rw] = pw0.z; Ws[buf][khw + 3][rw] = pw0.w;

        if (it + 1 < 32) {
            const float* Ap2 = Ap + (it + 1) * 16;
            pa0 = *(const float4*)Ap2;
            pa1 = *(const float4*)(Ap2 + 4);
            pw0 = *(const float4*)(Wp + (it + 1) * 16);
        }
        __syncthreads();

        #pragma unroll
        for (int ks = 0; ks < 16; ks += 8) {
            u32 af[4][4];
            #pragma unroll
            for (int mt = 0; mt < 4; ++mt) {
                int m = wm * 64 + mt * 16 + mr;
                af[mt][0] = tf32c(As[buf][ks + kc][m]);
                af[mt][1] = tf32c(As[buf][ks + kc][m + 8]);
                af[mt][2] = tf32c(As[buf][ks + kc + 4][m]);
                af[mt][3] = tf32c(As[buf][ks + kc + 4][m + 8]);
            }
            u32 bf[2][2];
            #pragma unroll
            for (int nt = 0; nt < 2; ++nt) {
                int n = wn * 16 + nt * 8 + mr;
                bf[nt][0] = tf32c(Ws[buf][ks + kc][n]);
                bf[nt][1] = tf32c(Ws[buf][ks + kc + 4][n]);
            }
            #pragma unroll
            for (int mt = 0; mt < 4; ++mt)
                #pragma unroll
                for (int nt = 0; nt < 2; ++nt) {
                    asm volatile(
                        "mma.sync.aligned.m16n8k8.row.col.f32.tf32.tf32.f32 "
                        "{%0,%1,%2,%3}, {%4,%5,%6,%7}, {%8,%9}, {%0,%1,%2,%3};"
                        : "+f"(acc[mt][nt][0]), "+f"(acc[mt][nt][1]),
                          "+f"(acc[mt][nt][2]), "+f"(acc[mt][nt][3])
                        : "r"(af[mt][0]), "r"(af[mt][1]),
                          "r"(af[mt][2]), "r"(af[mt][3]),
                          "r"(bf[nt][0]), "r"(bf[nt][1]));
                }
        }
        // no bottom sync: next iter's STS targets the other buffer.
    }

    float* Cp = g_com4[blockIdx.z];
    #pragma unroll
    for (int mt = 0; mt < 4; ++mt) {
        #pragma unroll
        for (int nt = 0; nt < 2; ++nt) {
            int row = m0 + wm * 64 + mt * 16 + mr;
            int col = n0 + wn * 16 + nt * 8 + 2 * kc;
            *(float2*)&Cp[(size_t)row * 512 + col] =
                make_float2(acc[mt][nt][0], acc[mt][nt][1]);
            *(float2*)&Cp[(size_t)(row + 8) * 512 + col] =
                make_float2(acc[mt][nt][2], acc[mt][nt][3]);
        }
    }
}

// ---------------------------------------------------------------------------
// Quantum circuit (R5-proven, 50.9us): 1 CTA per batch row, state (4096
// complex, AoS u64) in SMEM.  Wire w <-> bit (11 - w).
// Swizzle a(i) = i ^ ((i>>4) & 0xF).
// ---------------------------------------------------------------------------
__device__ __forceinline__ int swz(int i) { return i ^ ((i >> 4) & 0xF); }

// Packed complex 2x2 gate on pairs over local bit LB.
// c[8] splats: c[2e] = (m.x, m.x), c[2e+1] = (-m.y, m.y)  (negation folded).
// new = c0*A + c1*swap(A) + c2*B + c3*swap(B)   (per output half)
template<int LB>
__device__ __forceinline__ void rot2(u64* v, const u64* __restrict__ cf)
{
    u64 c0 = cf[0], c1 = cf[1], c2 = cf[2], c3 = cf[3];
    u64 c4 = cf[4], c5 = cf[5], c6 = cf[6], c7 = cf[7];
    #pragma unroll
    for (int p = 0; p < 8; ++p) {
        int k0 = ((p >> LB) << (LB + 1)) | (p & ((1 << LB) - 1));
        int k1 = k0 | (1 << LB);
        u64 A = v[k0], B = v[k1];
        u64 As_ = hswap(A), Bs = hswap(B);
        v[k0] = fma2(c0, A, fma2(c1, As_, fma2(c2, B, mul2(c3, Bs))));
        v[k1] = fma2(c4, A, fma2(c5, As_, fma2(c6, B, mul2(c7, Bs))));
    }
}

// Unscaled Hadamard butterfly (scale folded into final reduction).
template<int LB>
__device__ __forceinline__ void h2(u64* v, u64 neg1)
{
    #pragma unroll
    for (int p = 0; p < 8; ++p) {
        int k0 = ((p >> LB) << (LB + 1)) | (p & ((1 << LB) - 1));
        int k1 = k0 | (1 << LB);
        u64 A = v[k0], B = v[k1];
        v[k0] = add2(A, B);
        v[k1] = fma2(neg1, B, A);
    }
}

// Net gather index of the 12-CNOT chain with range R (GF(2)-linear).
template<int R>
__device__ __forceinline__ int cnotG(int i)
{
    #pragma unroll
    for (int w = 11; w >= 0; --w) {
        int pc = 11 - w;
        int pt = 11 - ((w + R) % 12);
        i ^= ((i >> pc) & 1) << pt;
    }
    return i;
}

__global__ __launch_bounds__(256, 2)
void circuit_kernel(const float* __restrict__ x,    // (1024, 2048) img angles
                    const float* __restrict__ bias, // (512,)
                    const float* __restrict__ qp,   // (2, 12, 3)
                    float* __restrict__ out)        // (1024,)
{
    __shared__ u64 st[4096];             // 32 KB state (packed complex)
    __shared__ u64 cf2[2][12][8];        // splatted gate coefficients
    __shared__ float red[8];

    const int t = threadIdx.x;
    const int b = blockIdx.x;
    const float* img = x + (size_t)b * 2048;
    const size_t crow = (size_t)b * 512;

    // --- Rot matrices, splatted: Rot = RZ(omega) RY(theta) RZ(phi) ---
    if (t < 24) {
        int l = t / 12, w = t % 12;
        float phi = qp[(l * 12 + w) * 3 + 0];
        float th  = qp[(l * 12 + w) * 3 + 1];
        float om  = qp[(l * 12 + w) * 3 + 2];
        float sh, ch;  sincosf(0.5f * th, &sh, &ch);
        float sa, ca;  sincosf(0.5f * (phi + om), &sa, &ca);
        float sb, cb;  sincosf(0.5f * (phi - om), &sb, &cb);
        u64* c = cf2[l][w];
        // m00 = (ch*ca, -ch*sa)
        c[0] = pk2( ch * ca,  ch * ca);
        c[1] = pk2( ch * sa, -ch * sa);
        // m01 = (-sh*cb, -sh*sb)
        c[2] = pk2(-sh * cb, -sh * cb);
        c[3] = pk2( sh * sb, -sh * sb);
        // m10 = (sh*cb, -sh*sb)
        c[4] = pk2( sh * cb,  sh * cb);
        c[5] = pk2( sh * sb, -sh * sb);
        // m11 = (ch*ca, ch*sa)
        c[6] = pk2( ch * ca,  ch * ca);
        c[7] = pk2(-ch * sa,  ch * sa);
    }
    __syncthreads();

    const u64 neg1 = pk2(-1.f, -1.f);
    u64 v[16];

    // ===== Pass 1 (nibble A: bits 0-3 local) : analytic FRQI(com), L0 Rots 11..8
    #pragma unroll
    for (int k = 0; k < 16; ++k) {
        int i = (t << 4) | k;
        if (i & 3) {
            v[k] = 0ull;
        } else {
            int j = (i >> 2) & 511;
            int aidx = __brev((unsigned)j) >> 23;
            float comv = bias[aidx];
            #pragma unroll
            for (int s = 0; s < SPLITK; ++s) comv += g_com4[s][crow + aidx];
            float sn, cs; __sincosf(0.5f * comv, &sn, &cs);
            float amp = ((i >> 11) & 1) ? sn : cs;
            v[k] = pk2(amp * 0.04419417382415922f, 0.f);  // 1/sqrt(512)
        }
    }
    rot2<0>(v, cf2[0][11]); rot2<1>(v, cf2[0][10]);
    rot2<2>(v, cf2[0][9]);  rot2<3>(v, cf2[0][8]);
    #pragma unroll
    for (int k = 0; k < 16; ++k) st[swz((t << 4) | k)] = v[k];
    __syncthreads();

    // ===== Pass 2 (B: bits 4-7) : L0 Rots 7..4
    #pragma unroll
    for (int k = 0; k < 16; ++k) v[k] = st[swz(((t >> 4) << 8) | (k << 4) | (t & 15))];
    rot2<0>(v, cf2[0][7]); rot2<1>(v, cf2[0][6]);
    rot2<2>(v, cf2[0][5]); rot2<3>(v, cf2[0][4]);
    #pragma unroll
    for (int k = 0; k < 16; ++k) st[swz(((t >> 4) << 8) | (k << 4) | (t & 15))] = v[k];
    __syncthreads();

    // ===== Pass 3 (C: bits 8-11) : L0 Rots 3..0
    #pragma unroll
    for (int k = 0; k < 16; ++k) v[k] = st[swz((k << 8) | t)];
    rot2<0>(v, cf2[0][3]); rot2<1>(v, cf2[0][2]);
    rot2<2>(v, cf2[0][1]); rot2<3>(v, cf2[0][0]);
    #pragma unroll
    for (int k = 0; k < 16; ++k) st[swz((k << 8) | t)] = v[k];
    __syncthreads();

    // ===== Pass 4 (A) : CNOT r=1 folded gather, L1 Rots 11..8
    {
        int base = cnotG<1>(t << 4);
        int m0 = cnotG<1>(1), m1 = cnotG<1>(2), m2 = cnotG<1>(4), m3 = cnotG<1>(8);
        #pragma unroll
        for (int k = 0; k < 16; ++k) {
            int gi = base ^ ((k & 1) ? m0 : 0) ^ ((k & 2) ? m1 : 0)
                          ^ ((k & 4) ? m2 : 0) ^ ((k & 8) ? m3 : 0);
            v[k] = st[swz(gi)];
        }
    }
    __syncthreads();
    rot2<0>(v, cf2[1][11]); rot2<1>(v, cf2[1][10]);
    rot2<2>(v, cf2[1][9]);  rot2<3>(v, cf2[1][8]);
    #pragma unroll
    for (int k = 0; k < 16; ++k) st[swz((t << 4) | k)] = v[k];
    __syncthreads();

    // ===== Pass 5 (B) : L1 Rots 7..4
    #pragma unroll
    for (int k = 0; k < 16; ++k) v[k] = st[swz(((t >> 4) << 8) | (k << 4) | (t & 15))];
    rot2<0>(v, cf2[1][7]); rot2<1>(v, cf2[1][6]);
    rot2<2>(v, cf2[1][5]); rot2<3>(v, cf2[1][4]);
    #pragma unroll
    for (int k = 0; k < 16; ++k) st[swz(((t >> 4) << 8) | (k << 4) | (t & 15))] = v[k];
    __syncthreads();

    // ===== Pass 6 (C) : L1 Rots 3..0
    #pragma unroll
    for (int k = 0; k < 16; ++k) v[k] = st[swz((k << 8) | t)];
    rot2<0>(v, cf2[1][3]); rot2<1>(v, cf2[1][2]);
    rot2<2>(v, cf2[1][1]); rot2<3>(v, cf2[1][0]);
    #pragma unroll
    for (int k = 0; k < 16; ++k) st[swz((k << 8) | t)] = v[k];
    __syncthreads();

    // ===== Pass 7 (A) : CNOT r=2 folded gather, H bits 0-3 (unscaled)
    {
        int base = cnotG<2>(t << 4);
        int m0 = cnotG<2>(1), m1 = cnotG<2>(2), m2 = cnotG<2>(4), m3 = cnotG<2>(8);
        #pragma unroll
        for (int k = 0; k < 16; ++k) {
            int gi = base ^ ((k & 1) ? m0 : 0) ^ ((k & 2) ? m1 : 0)
                          ^ ((k & 4) ? m2 : 0) ^ ((k & 8) ? m3 : 0);
            v[k] = st[swz(gi)];
        }
    }
    __syncthreads();
    h2<0>(v, neg1); h2<1>(v, neg1); h2<2>(v, neg1); h2<3>(v, neg1);
    #pragma unroll
    for (int k = 0; k < 16; ++k) st[swz((t << 4) | k)] = v[k];
    __syncthreads();

    // ===== Pass 8 (B) : H bits 4-7 (unscaled)
    #pragma unroll
    for (int k = 0; k < 16; ++k) v[k] = st[swz(((t >> 4) << 8) | (k << 4) | (t & 15))];
    h2<0>(v, neg1); h2<1>(v, neg1); h2<2>(v, neg1); h2<3>(v, neg1);
    #pragma unroll
    for (int k = 0; k < 16; ++k) st[swz(((t >> 4) << 8) | (k << 4) | (t & 15))] = v[k];
    __syncthreads();

    // ===== Pass 9 (C) : H bits 8-10 (unscaled), UC-RY(img) on wire 0, measure
    #pragma unroll
    for (int k = 0; k < 16; ++k) v[k] = st[swz((k << 8) | t)];
    h2<0>(v, neg1); h2<1>(v, neg1); h2<2>(v, neg1);

    #pragma unroll
    for (int k0 = 0; k0 < 8; ++k0) {
        int i0 = (k0 << 8) | t;
        int aidx = __brev((unsigned)i0) >> 21;
        float sn, cs; __sincosf(0.5f * img[aidx], &sn, &cs);
        u64 A = v[k0], B = v[k0 + 8];
        u64 cs2 = pk2(cs, cs), sn2 = pk2(sn, sn), sn2n = pk2(-sn, -sn);
        v[k0]     = fma2(cs2, A, mul2(sn2n, B));
        v[k0 + 8] = fma2(sn2, A, mul2(cs2, B));
    }

    u64 accN = 0ull, accP = 0ull;
    #pragma unroll
    for (int k = 0; k < 8; ++k)  accN = fma2(v[k], v[k], accN);
    #pragma unroll
    for (int k = 8; k < 16; ++k) accP = fma2(v[k], v[k], accP);
    float pl, ph, nl, nh;
    unpk2(pl, ph, accP); unpk2(nl, nh, accN);
    float acc = (pl + ph) - (nl + nh);

    #pragma unroll
    for (int o = 16; o; o >>= 1) acc += __shfl_xor_sync(0xffffffffu, acc, o);
    if ((t & 31) == 0) red[t >> 5] = acc;
    __syncthreads();
    if (t == 0) {
        float s = 0.f;
        #pragma unroll
        for (int w = 0; w < 8; ++w) s += red[w];
        out[b] = s * (1.0f / 2048.0f);   // fold (1/sqrt(2))^11 (squared) scale
    }
}

// ---------------------------------------------------------------------------
extern "C" void kernel_launch(void* const* d_in, const int* in_sizes, int n_in,
                              void* d_out, int out_size)
{
    const float* x  = (const float*)d_in[0];   // (1024, 2, 32, 32) -> (1024, 2048)
    const float* Wm = (const float*)d_in[1];   // (512, 2048)
    const float* bb = (const float*)d_in[2];   // (512,)
    const float* qp = (const float*)d_in[3];   // (2, 12, 3)
    float* out = (float*)d_out;                // (1024,)

    dim3 gemm_grid(512 / 64, 1024 / 128, SPLITK);   // (8, 8, 4) = 256 CTAs
    gemm_tc<<<gemm_grid, 256>>>(x, Wm);
    circuit_kernel<<<1024, 256>>>(x, bb, qp, out);
}